// round 5
// baseline (speedup 1.0000x reference)
#include <cuda_runtime.h>
#include <math.h>
#include <stdint.h>

// ---------------------------------------------------------------------------
// MultiHeadCrossAttentionBlock: B=4, S=2048, D=512, H=8, DK=64
// d_out = out [B,S,D] ++ attn.mean(axis=1) [B,S,S]  (floats, concatenated)
//
// Round 4: k5 -> warp-level tensor cores (mma.sync m16n8k8 tf32), 3-pass
// hi/lo split for fp32-grade accuracy on the out-projection (no argmax
// exposure on this chain). Operands staged in fragment-order smem with
// interleaved hi/lo so each fragment load is a single conflict-free LDS.128.
// k1/k2 unchanged from round 3 (k1 measured at the fp32 3-reg FFMA roof;
// k2 within ~12% of its dual-saturation floor).
// ---------------------------------------------------------------------------

namespace cfg {
constexpr int B  = 4;
constexpr int S  = 2048;
constexpr int D  = 512;
constexpr int H  = 8;
constexpr int DK = 64;
constexpr int N3 = 3 * D;          // 1536
constexpr int MROWS = B * S;       // 8192
constexpr float SCALE = 0.125f;    // DK^-0.5
constexpr int TQ = 16;             // q rows per block
constexpr int TK = 256;            // k/v chunk length
constexpr int NCH = S / TK;        // 8 chunks
constexpr int SROW = S + 4;        // padded Ss row stride (floats)
constexpr int SMEM2_FLOATS = TQ * SROW + DK * TK + DK * 20;
constexpr int SMEM2 = SMEM2_FLOATS * 4;   // 201,984 bytes
// k5 mma config
constexpr int K5_BK = 32;                  // k per tile (4 k-frags of 8)
constexpr int K5_SMEM = 2 * 8192 * 4;      // AF + BF = 64 KB
}

// ------------------------------ scratch (64 MB total) ----------------------
__device__ float g_Q [cfg::B * cfg::H * cfg::S * cfg::DK];   // [b,h,s,dk]
__device__ float g_Kt[cfg::B * cfg::H * cfg::DK * cfg::S];   // [b,h,dk,s]
__device__ float g_V [cfg::B * cfg::H * cfg::S * cfg::DK];   // [b,h,s,dk]
__device__ float g_ctx[cfg::B * cfg::S * cfg::D];            // [b,s,h*DK+dk]

// ---------------------------------------------------------------------------
// tf32 helpers
// ---------------------------------------------------------------------------
__device__ __forceinline__ float tf32_rna(float x) {
    uint32_t u;
    asm("cvt.rna.tf32.f32 %0, %1;" : "=r"(u) : "f"(x));
    return __uint_as_float(u);
}

__device__ __forceinline__ void mma_tf32(
    float& d0, float& d1, float& d2, float& d3,
    float a0, float a1, float a2, float a3, float b0, float b1)
{
    asm volatile(
        "mma.sync.aligned.m16n8k8.row.col.f32.tf32.tf32.f32 "
        "{%0,%1,%2,%3}, {%4,%5,%6,%7}, {%8,%9}, {%0,%1,%2,%3};"
        : "+f"(d0), "+f"(d1), "+f"(d2), "+f"(d3)
        : "r"(__float_as_uint(a0)), "r"(__float_as_uint(a1)),
          "r"(__float_as_uint(a2)), "r"(__float_as_uint(a3)),
          "r"(__float_as_uint(b0)), "r"(__float_as_uint(b1)));
}

// ---------------------------------------------------------------------------
// K1: QKV projection. C[8192,1536] = Z @ Wqkv  (Z = Zq for n<512, else Zkv)
// (unchanged; measured at the fp32 3-reg FFMA roof)
// ---------------------------------------------------------------------------
__global__ __launch_bounds__(256) void k1_qkv(
    const float* __restrict__ Zq, const float* __restrict__ Zkv,
    const float* __restrict__ W)
{
    using namespace cfg;
    constexpr int BM = 128, BN = 128, BK = 16;
    __shared__ float As[BK][BM + 4];
    __shared__ float Bs[BK][BN];

    const int row0 = blockIdx.x * BM;
    const int col0 = blockIdx.y * BN;
    const float* __restrict__ Z = (col0 < D) ? Zq : Zkv;

    const int t  = threadIdx.x;
    const int tm = (t >> 4) << 3;
    const int tn = (t & 15) << 3;

    float acc[8][8];
#pragma unroll
    for (int i = 0; i < 8; i++)
#pragma unroll
        for (int j = 0; j < 8; j++) acc[i][j] = 0.f;

    for (int k0 = 0; k0 < D; k0 += BK) {
#pragma unroll
        for (int i = 0; i < 8; i++) {           // A tile: 128x16
            int p = t + i * 256;
            int m = p >> 4, k = p & 15;
            As[k][m] = Z[(size_t)(row0 + m) * D + k0 + k];
        }
#pragma unroll
        for (int i = 0; i < 8; i++) {           // B tile: 16x128
            int p = t + i * 256;
            int k = p >> 7, n = p & 127;
            Bs[k][n] = W[(size_t)(k0 + k) * N3 + col0 + n];
        }
        __syncthreads();
#pragma unroll
        for (int k = 0; k < BK; k++) {
            float a[8], b[8];
#pragma unroll
            for (int i = 0; i < 8; i++) a[i] = As[k][tm + i];
#pragma unroll
            for (int j = 0; j < 8; j++) b[j] = Bs[k][tn + j];
#pragma unroll
            for (int i = 0; i < 8; i++)
#pragma unroll
                for (int j = 0; j < 8; j++)
                    acc[i][j] = fmaf(a[i], b[j], acc[i][j]);
        }
        __syncthreads();
    }

    const int part = col0 / D;                  // 0=Q, 1=K, 2=V (block-uniform)
#pragma unroll
    for (int i = 0; i < 8; i++) {
        const int r = row0 + tm + i;
        const int b = r >> 11, s = r & (S - 1);
#pragma unroll
        for (int j = 0; j < 8; j++) {
            const int c  = col0 + tn + j - part * D;
            const int h  = c >> 6, dk = c & 63;
            const float v = acc[i][j];
            if (part == 0)      g_Q [((size_t)(b * H + h) * S  + s)  * DK + dk] = v;
            else if (part == 1) g_Kt[((size_t)(b * H + h) * DK + dk) * S  + s ] = v;
            else                g_V [((size_t)(b * H + h) * S  + s)  * DK + dk] = v;
        }
    }
}

// ---------------------------------------------------------------------------
// K2: fused attention. Grid (S/TQ=128, B=4), 256 threads, ~197 KB dyn smem.
// (unchanged from round 3)
// ---------------------------------------------------------------------------
__global__ __launch_bounds__(256, 1) void k2_attn(
    const float* __restrict__ mask, float* __restrict__ attn_out)
{
    using namespace cfg;
    extern __shared__ float sm[];
    float* Ss  = sm;                      // [TQ][SROW]  scores / probs
    float* KVs = Ss + TQ * SROW;          // K chunk / V chunk / partials
    float* Qs  = KVs + DK * TK;           // [DK][20]    d-major Q tile

    const int qt = blockIdx.x;
    const int b  = blockIdx.y;
    const int q0 = qt * TQ;
    const int t  = threadIdx.x;

    const int qi = t >> 6;                // 0..3
    const int ki = t & 63;                // 0..63
    const int kq  = t >> 6;               // 0..3  k-quarter group
    const int qg4 = ((t >> 4) & 3) << 2;  // q row base
    const int cg4 = (t & 15) << 2;        // col base
    const int w = t >> 5, lane = t & 31;

    float4 pf[16];

    for (int h = 0; h < H; h++) {
        const int bh = b * H + h;
        const float* __restrict__ Qg  = g_Q  + ((size_t)bh * S + q0) * DK;
        const float* __restrict__ Ktg = g_Kt + (size_t)bh * DK * S;
        const float* __restrict__ Vg  = g_V  + (size_t)bh * S * DK;

#pragma unroll
        for (int i = 0; i < 4; i++) {
            int p = t + i * 256;
            int q = p >> 6, d = p & 63;
            Qs[d * 20 + q] = Qg[q * DK + d];
        }

#pragma unroll
        for (int i = 0; i < 16; i++) {
            int p4 = t + (i << 8);
            pf[i] = *(const float4*)&Ktg[(size_t)(p4 >> 6) * S + ((p4 & 63) << 2)];
        }

        for (int c = 0; c < NCH; c++) {
            const int kc = c * TK;
            __syncthreads();
#pragma unroll
            for (int i = 0; i < 16; i++) {
                int p4 = t + (i << 8);
                *(float4*)&KVs[(p4 >> 6) * TK + ((p4 & 63) << 2)] = pf[i];
            }
            if (c < NCH - 1) {
#pragma unroll
                for (int i = 0; i < 16; i++) {
                    int p4 = t + (i << 8);
                    pf[i] = *(const float4*)&Ktg[(size_t)(p4 >> 6) * S + kc + TK + ((p4 & 63) << 2)];
                }
            } else {
#pragma unroll
                for (int i = 0; i < 16; i++) {
                    int p4 = t + (i << 8);
                    pf[i] = *(const float4*)&Vg[(size_t)(p4 >> 4) * DK + ((p4 & 15) << 2)];
                }
            }
            __syncthreads();

            float acc[4][4];
#pragma unroll
            for (int i = 0; i < 4; i++)
#pragma unroll
                for (int j = 0; j < 4; j++) acc[i][j] = 0.f;

#pragma unroll
            for (int d = 0; d < DK; d++) {
                const float4 kv = *(const float4*)&KVs[d * TK + (ki << 2)];
                const float4 qv = *(const float4*)&Qs[d * 20 + (qi << 2)];
                acc[0][0] = fmaf(qv.x, kv.x, acc[0][0]);
                acc[0][1] = fmaf(qv.x, kv.y, acc[0][1]);
                acc[0][2] = fmaf(qv.x, kv.z, acc[0][2]);
                acc[0][3] = fmaf(qv.x, kv.w, acc[0][3]);
                acc[1][0] = fmaf(qv.y, kv.x, acc[1][0]);
                acc[1][1] = fmaf(qv.y, kv.y, acc[1][1]);
                acc[1][2] = fmaf(qv.y, kv.z, acc[1][2]);
                acc[1][3] = fmaf(qv.y, kv.w, acc[1][3]);
                acc[2][0] = fmaf(qv.z, kv.x, acc[2][0]);
                acc[2][1] = fmaf(qv.z, kv.y, acc[2][1]);
                acc[2][2] = fmaf(qv.z, kv.z, acc[2][2]);
                acc[2][3] = fmaf(qv.z, kv.w, acc[2][3]);
                acc[3][0] = fmaf(qv.w, kv.x, acc[3][0]);
                acc[3][1] = fmaf(qv.w, kv.y, acc[3][1]);
                acc[3][2] = fmaf(qv.w, kv.z, acc[3][2]);
                acc[3][3] = fmaf(qv.w, kv.w, acc[3][3]);
            }

#pragma unroll
            for (int i = 0; i < 4; i++) {
                const int q = (qi << 2) + i;
                const float4 mk = *(const float4*)&mask[(size_t)(q0 + q) * S + kc + (ki << 2)];
                float4 o;
                o.x = fmaf(acc[i][0], SCALE, mk.x);
                o.y = fmaf(acc[i][1], SCALE, mk.y);
                o.z = fmaf(acc[i][2], SCALE, mk.z);
                o.w = fmaf(acc[i][3], SCALE, mk.w);
                *(float4*)&Ss[q * SROW + kc + (ki << 2)] = o;
            }
        }
        __syncthreads();

#pragma unroll
        for (int i = 0; i < 16; i++) {
            int p4 = t + (i << 8);
            *(float4*)&KVs[(p4 >> 4) * DK + ((p4 & 15) << 2)] = pf[i];
        }
#pragma unroll
        for (int i = 0; i < 16; i++) {
            int p4 = t + (i << 8);
            pf[i] = *(const float4*)&Vg[(size_t)(TK + (p4 >> 4)) * DK + ((p4 & 15) << 2)];
        }

#pragma unroll
        for (int rr = 0; rr < 2; rr++) {
            const int q = w * 2 + rr;
            float* row = Ss + q * SROW;
            float m = -1e30f;
            for (int i = lane; i < S; i += 32) m = fmaxf(m, row[i]);
#pragma unroll
            for (int o = 16; o; o >>= 1) m = fmaxf(m, __shfl_xor_sync(0xFFFFFFFFu, m, o));
            float l = 0.f;
            for (int i = lane; i < S; i += 32) {
                float e = __expf(row[i] - m);
                row[i] = e;
                l += e;
            }
#pragma unroll
            for (int o = 16; o; o >>= 1) l += __shfl_xor_sync(0xFFFFFFFFu, l, o);
            const float inv = 1.f / l;

            float* __restrict__ arow = attn_out + ((size_t)b * S + q0 + q) * S;
            for (int i = lane * 4; i < S; i += 128) {
                float4 e = *(float4*)&row[i];
                e.x *= inv; e.y *= inv; e.z *= inv; e.w *= inv;
                *(float4*)&row[i] = e;
                float4 a;
                a.x = e.x * 0.125f; a.y = e.y * 0.125f;
                a.z = e.z * 0.125f; a.w = e.w * 0.125f;
                if (h > 0) {
                    float4 prev = *(float4*)&arow[i];
                    a.x += prev.x; a.y += prev.y; a.z += prev.z; a.w += prev.w;
                }
                *(float4*)&arow[i] = a;
            }
        }
        __syncthreads();

        float4 cacc[4];
#pragma unroll
        for (int i = 0; i < 4; i++) cacc[i] = make_float4(0.f, 0.f, 0.f, 0.f);

        for (int c = 0; c < NCH; c++) {
            const int vc = c * TK;
            const int kb = vc + (kq << 6);
#pragma unroll
            for (int kk = 0; kk < 64; kk += 4) {
                const float4 v0 = *(const float4*)&KVs[((kq << 6) + kk + 0) * DK + cg4];
                const float4 v1 = *(const float4*)&KVs[((kq << 6) + kk + 1) * DK + cg4];
                const float4 v2 = *(const float4*)&KVs[((kq << 6) + kk + 2) * DK + cg4];
                const float4 v3 = *(const float4*)&KVs[((kq << 6) + kk + 3) * DK + cg4];
#pragma unroll
                for (int i = 0; i < 4; i++) {
                    const float4 p = *(const float4*)&Ss[(qg4 + i) * SROW + kb + kk];
                    cacc[i].x = fmaf(p.x, v0.x, cacc[i].x);
                    cacc[i].y = fmaf(p.x, v0.y, cacc[i].y);
                    cacc[i].z = fmaf(p.x, v0.z, cacc[i].z);
                    cacc[i].w = fmaf(p.x, v0.w, cacc[i].w);
                    cacc[i].x = fmaf(p.y, v1.x, cacc[i].x);
                    cacc[i].y = fmaf(p.y, v1.y, cacc[i].y);
                    cacc[i].z = fmaf(p.y, v1.z, cacc[i].z);
                    cacc[i].w = fmaf(p.y, v1.w, cacc[i].w);
                    cacc[i].x = fmaf(p.z, v2.x, cacc[i].x);
                    cacc[i].y = fmaf(p.z, v2.y, cacc[i].y);
                    cacc[i].z = fmaf(p.z, v2.z, cacc[i].z);
                    cacc[i].w = fmaf(p.z, v2.w, cacc[i].w);
                    cacc[i].x = fmaf(p.w, v3.x, cacc[i].x);
                    cacc[i].y = fmaf(p.w, v3.y, cacc[i].y);
                    cacc[i].z = fmaf(p.w, v3.z, cacc[i].z);
                    cacc[i].w = fmaf(p.w, v3.w, cacc[i].w);
                }
            }
            if (c < NCH - 1) {
                __syncthreads();
#pragma unroll
                for (int i = 0; i < 16; i++) {
                    int p4 = t + (i << 8);
                    *(float4*)&KVs[(p4 >> 4) * DK + ((p4 & 15) << 2)] = pf[i];
                }
                if (c < NCH - 2) {
#pragma unroll
                    for (int i = 0; i < 16; i++) {
                        int p4 = t + (i << 8);
                        pf[i] = *(const float4*)&Vg[(size_t)((vc + 2 * TK) + (p4 >> 4)) * DK + ((p4 & 15) << 2)];
                    }
                }
                __syncthreads();
            }
        }

        __syncthreads();
#pragma unroll
        for (int i = 0; i < 4; i++)
            *(float4*)&KVs[(kq << 10) + (qg4 + i) * DK + cg4] = cacc[i];
        __syncthreads();
        {
            const int q  = t >> 4;
            const int c4 = (t & 15) << 2;
            float4 s0 = *(const float4*)&KVs[0 * 1024 + q * DK + c4];
            float4 s1 = *(const float4*)&KVs[1 * 1024 + q * DK + c4];
            float4 s2 = *(const float4*)&KVs[2 * 1024 + q * DK + c4];
            float4 s3 = *(const float4*)&KVs[3 * 1024 + q * DK + c4];
            float4 o;
            o.x = (s0.x + s1.x) + (s2.x + s3.x);
            o.y = (s0.y + s1.y) + (s2.y + s3.y);
            o.z = (s0.z + s1.z) + (s2.z + s3.z);
            o.w = (s0.w + s1.w) + (s2.w + s3.w);
            *(float4*)&g_ctx[((size_t)b * S + q0 + q) * D + h * DK + c4] = o;
        }
    }
}

// ---------------------------------------------------------------------------
// K5 (tensor): out[8192,512] = ctx @ Wout via mma.sync m16n8k8 tf32, 3-pass
// hi/lo split. Block 128x128, 256 threads = 8 warps (2m x 4n), warp tile
// 64x32 (4 m-frags x 4 n-frags). BK=32 (4 k-frags).
//
// Operands staged in FRAGMENT ORDER with interleaved (hi,lo):
//  AF[kf][mfg(8)][rowhalf(2)][lane(32)] : float4 = {hi(c), lo(c), hi(c+4), lo(c+4)}
//       lane = r*4 + c  (r = groupID 0..7, c = threadID 0..3)
//  BF[kf][nfg(16)][lane(32)]            : float4 = {b0h, b0l, b1h, b1l}
//       lane = n*4 + kc (n = groupID 0..7, kc = threadID 0..3)
// Every fragment load = one LDS.128, lanes contiguous => conflict-free.
// ---------------------------------------------------------------------------
__global__ __launch_bounds__(256, 1) void k5_out_mma(
    const float* __restrict__ Wout, float* __restrict__ out)
{
    using namespace cfg;
    constexpr int BM = 128, BN = 128, BK = K5_BK;   // 128x128x32
    extern __shared__ float sm5[];
    float* AF = sm5;              // 4*8*2*32*4 = 8192 floats (32 KB)
    float* BF = sm5 + 8192;       // 4*16*32*4  = 8192 floats (32 KB)

    const int row0 = blockIdx.x * BM;
    const int col0 = blockIdx.y * BN;
    const int t    = threadIdx.x;
    const int wrp  = t >> 5;
    const int lane = t & 31;
    const int wm   = wrp >> 2;            // 0..1 -> m offset 64*wm
    const int wn   = wrp & 3;             // 0..3 -> n offset 32*wn
    const int gID  = lane >> 2;           // groupID 0..7
    const int tc   = lane & 3;            // threadID-in-group

    float acc[4][4][4];
#pragma unroll
    for (int i = 0; i < 4; i++)
#pragma unroll
        for (int j = 0; j < 4; j++)
#pragma unroll
            for (int r = 0; r < 4; r++) acc[i][j][r] = 0.f;

    float4 pfA[4], pfB[4];

    // prefetch tile 0
#pragma unroll
    for (int i = 0; i < 4; i++) {
        int j = t + i * 256;                        // 0..1023
        int m = j >> 3, kq = j & 7;                 // A: 128 rows x 8 float4
        pfA[i] = *(const float4*)&g_ctx[(size_t)(row0 + m) * D + (kq << 2)];
        int kl = j >> 5, nq = j & 31;               // B: 32 rows x 32 float4
        pfB[i] = *(const float4*)&Wout[(size_t)kl * D + col0 + (nq << 2)];
    }

    for (int kt = 0; kt < D / BK; kt++) {
        __syncthreads();                            // smem free (prev compute done)

        // ---- stage prefetched tile into fragment-order smem (hi/lo split) --
#pragma unroll
        for (int i = 0; i < 4; i++) {
            int j = t + i * 256;
            {   // A element group: row m, k-cols kq*4..kq*4+3
                int m = j >> 3, kq = j & 7;
                const int mfg = m >> 4;
                const int rh  = (m >> 3) & 1;
                const int r   = m & 7;
                const float v[4] = {pfA[i].x, pfA[i].y, pfA[i].z, pfA[i].w};
#pragma unroll
                for (int e = 0; e < 4; e++) {
                    int kl = (kq << 2) + e;
                    int kf = kl >> 3, ch = (kl >> 2) & 1, c = kl & 3;
                    float hi = tf32_rna(v[e]);
                    float lo = tf32_rna(v[e] - hi);
                    int adr = ((((kf << 3) + mfg) * 2 + rh) * 32 + (r << 2) + c) * 4 + (ch << 1);
                    *(float2*)&AF[adr] = make_float2(hi, lo);
                }
            }
            {   // B element group: k-row kl, n-cols nq*4..nq*4+3
                int kl = j >> 5, nq = j & 31;
                const int kf = kl >> 3, ch = (kl >> 2) & 1, c = kl & 3;
                const float v[4] = {pfB[i].x, pfB[i].y, pfB[i].z, pfB[i].w};
#pragma unroll
                for (int e = 0; e < 4; e++) {
                    int nl  = (nq << 2) + e;
                    int nfg = nl >> 3, g = nl & 7;
                    float hi = tf32_rna(v[e]);
                    float lo = tf32_rna(v[e] - hi);
                    int adr = (((kf << 4) + nfg) * 32 + (g << 2) + c) * 4 + (ch << 1);
                    *(float2*)&BF[adr] = make_float2(hi, lo);
                }
            }
        }
        __syncthreads();

        // ---- prefetch next tile (overlaps mma compute) ----
        if (kt < D / BK - 1) {
            const int k0n = (kt + 1) * BK;
#pragma unroll
            for (int i = 0; i < 4; i++) {
                int j = t + i * 256;
                int m = j >> 3, kq = j & 7;
                pfA[i] = *(const float4*)&g_ctx[(size_t)(row0 + m) * D + k0n + (kq << 2)];
                int kl = j >> 5, nq = j & 31;
                pfB[i] = *(const float4*)&Wout[(size_t)(k0n + kl) * D + col0 + (nq << 2)];
            }
        }

        // ---- mma over 4 k-frags ----
#pragma unroll
        for (int kf = 0; kf < 4; kf++) {
            float4 a0[4], a1[4];                    // per m-frag: rowhalf 0/1
#pragma unroll
            for (int mf = 0; mf < 4; mf++) {
                const int mfg = (wm << 2) + mf;
                a0[mf] = *(const float4*)&AF[((((kf << 3) + mfg) * 2 + 0) * 32 + lane) * 4];
                a1[mf] = *(const float4*)&AF[((((kf << 3) + mfg) * 2 + 1) * 32 + lane) * 4];
            }
            float4 bb[4];
#pragma unroll
            for (int nf = 0; nf < 4; nf++) {
                const int nfg = (wn << 2) + nf;
                bb[nf] = *(const float4*)&BF[(((kf << 4) + nfg) * 32 + lane) * 4];
            }
#pragma unroll
            for (int mf = 0; mf < 4; mf++) {
#pragma unroll
                for (int nf = 0; nf < 4; nf++) {
                    float* d = acc[mf][nf];
                    // hi*hi
                    mma_tf32(d[0], d[1], d[2], d[3],
                             a0[mf].x, a1[mf].x, a0[mf].z, a1[mf].z,
                             bb[nf].x, bb[nf].z);
                    // hi*lo
                    mma_tf32(d[0], d[1], d[2], d[3],
                             a0[mf].x, a1[mf].x, a0[mf].z, a1[mf].z,
                             bb[nf].y, bb[nf].w);
                    // lo*hi
                    mma_tf32(d[0], d[1], d[2], d[3],
                             a0[mf].y, a1[mf].y, a0[mf].w, a1[mf].w,
                             bb[nf].x, bb[nf].z);
                }
            }
        }
    }

    // ---- epilogue: C frags -> gmem ----
#pragma unroll
    for (int mf = 0; mf < 4; mf++) {
        const int r0 = row0 + (wm << 6) + (mf << 4) + gID;
#pragma unroll
        for (int nf = 0; nf < 4; nf++) {
            const int c0 = col0 + (wn << 5) + (nf << 3) + (tc << 1);
            *(float2*)&out[(size_t)r0 * D + c0] =
                make_float2(acc[mf][nf][0], acc[mf][nf][1]);
            *(float2*)&out[(size_t)(r0 + 8) * D + c0] =
                make_float2(acc[mf][nf][2], acc[mf][nf][3]);
        }
    }
}

// ---------------------------------------------------------------------------
namespace {
struct CudaWarm {
    CudaWarm() {
        cudaFuncSetAttribute(k2_attn,
            cudaFuncAttributeMaxDynamicSharedMemorySize, cfg::SMEM2);
        cudaFuncSetAttribute(k5_out_mma,
            cudaFuncAttributeMaxDynamicSharedMemorySize, cfg::K5_SMEM);
        cudaFuncAttributes a;
        cudaFuncGetAttributes(&a, (const void*)k1_qkv);
        cudaFuncGetAttributes(&a, (const void*)k2_attn);
        cudaFuncGetAttributes(&a, (const void*)k5_out_mma);
    }
};
CudaWarm g_warm;
}

// ---------------------------------------------------------------------------
extern "C" void kernel_launch(void* const* d_in, const int* in_sizes, int n_in,
                              void* d_out, int out_size)
{
    using namespace cfg;
    const float* Zq   = (const float*)d_in[0];
    const float* Zkv  = (const float*)d_in[1];
    const float* mask = (const float*)d_in[2];
    const float* Wqkv = (const float*)d_in[3];
    const float* Wout = (const float*)d_in[4];

    float* out       = (float*)d_out;
    float* attn_mean = out + (size_t)B * S * D;

    cudaFuncSetAttribute(k2_attn,
        cudaFuncAttributeMaxDynamicSharedMemorySize, SMEM2);
    cudaFuncSetAttribute(k5_out_mma,
        cudaFuncAttributeMaxDynamicSharedMemorySize, K5_SMEM);

    k1_qkv<<<dim3(MROWS / 128, N3 / 128), 256>>>(Zq, Zkv, Wqkv);
    k2_attn<<<dim3(S / TQ, B), 256, SMEM2>>>(mask, attn_mean);
    k5_out_mma<<<dim3(MROWS / 128, D / 128), 256, K5_SMEM>>>(Wout, out);
}

// round 6
// speedup vs baseline: 1.1695x; 1.1695x over previous
#include <cuda_runtime.h>
#include <math.h>

// ---------------------------------------------------------------------------
// MultiHeadCrossAttentionBlock: B=4, S=2048, D=512, H=8, DK=64
// d_out = out [B,S,D] ++ attn.mean(axis=1) [B,S,S]  (floats, concatenated)
//
// Round 5:
//  * k5 reverted to FFMA (R4 showed legacy mma.sync tf32 is SLOWER: ~240us
//    vs ~120us; tensor path on sm_103a must be tcgen05 or nothing).
//  * k2 head-loop split in two (grid z=2: h 0-3 vs h 4-7) => 1024 equal
//    blocks = 6.92 waves instead of 512 blocks = 3.46 waves (15% tail -> 1%).
//    z=1 accumulates attn_mean partials into a private scratch buffer;
//    a small merge kernel adds it into the output (race-free).
// ---------------------------------------------------------------------------

namespace cfg {
constexpr int B  = 4;
constexpr int S  = 2048;
constexpr int D  = 512;
constexpr int H  = 8;
constexpr int DK = 64;
constexpr int N3 = 3 * D;          // 1536
constexpr int MROWS = B * S;       // 8192
constexpr float SCALE = 0.125f;    // DK^-0.5
constexpr int TQ = 16;             // q rows per block
constexpr int TK = 256;            // k/v chunk length
constexpr int NCH = S / TK;        // 8 chunks
constexpr int SROW = S + 4;        // padded Ss row stride (floats)
constexpr int SMEM2_FLOATS = TQ * SROW + DK * TK + DK * 20;
constexpr int SMEM2 = SMEM2_FLOATS * 4;   // 201,984 bytes
constexpr int HGRP = H / 2;        // heads per z-group
}

// ------------------------------ scratch ------------------------------------
__device__ float g_Q [cfg::B * cfg::H * cfg::S * cfg::DK];   // [b,h,s,dk]
__device__ float g_Kt[cfg::B * cfg::H * cfg::DK * cfg::S];   // [b,h,dk,s]
__device__ float g_V [cfg::B * cfg::H * cfg::S * cfg::DK];   // [b,h,s,dk]
__device__ float g_ctx[cfg::B * cfg::S * cfg::D];            // [b,s,h*DK+dk]
__device__ float g_attn2[(size_t)cfg::B * cfg::S * cfg::S];  // 64 MB partials (h 4-7)

// ---------------------------------------------------------------------------
// K1: QKV projection. C[8192,1536] = Z @ Wqkv  (Z = Zq for n<512, else Zkv)
// ---------------------------------------------------------------------------
__global__ __launch_bounds__(256) void k1_qkv(
    const float* __restrict__ Zq, const float* __restrict__ Zkv,
    const float* __restrict__ W)
{
    using namespace cfg;
    constexpr int BM = 128, BN = 128, BK = 16;
    __shared__ float As[BK][BM + 4];
    __shared__ float Bs[BK][BN];

    const int row0 = blockIdx.x * BM;
    const int col0 = blockIdx.y * BN;
    const float* __restrict__ Z = (col0 < D) ? Zq : Zkv;

    const int t  = threadIdx.x;
    const int tm = (t >> 4) << 3;
    const int tn = (t & 15) << 3;

    float acc[8][8];
#pragma unroll
    for (int i = 0; i < 8; i++)
#pragma unroll
        for (int j = 0; j < 8; j++) acc[i][j] = 0.f;

    for (int k0 = 0; k0 < D; k0 += BK) {
#pragma unroll
        for (int i = 0; i < 8; i++) {           // A tile: 128x16
            int p = t + i * 256;
            int m = p >> 4, k = p & 15;
            As[k][m] = Z[(size_t)(row0 + m) * D + k0 + k];
        }
#pragma unroll
        for (int i = 0; i < 8; i++) {           // B tile: 16x128
            int p = t + i * 256;
            int k = p >> 7, n = p & 127;
            Bs[k][n] = W[(size_t)(k0 + k) * N3 + col0 + n];
        }
        __syncthreads();
#pragma unroll
        for (int k = 0; k < BK; k++) {
            float a[8], b[8];
#pragma unroll
            for (int i = 0; i < 8; i++) a[i] = As[k][tm + i];
#pragma unroll
            for (int j = 0; j < 8; j++) b[j] = Bs[k][tn + j];
#pragma unroll
            for (int i = 0; i < 8; i++)
#pragma unroll
                for (int j = 0; j < 8; j++)
                    acc[i][j] = fmaf(a[i], b[j], acc[i][j]);
        }
        __syncthreads();
    }

    const int part = col0 / D;                  // 0=Q, 1=K, 2=V (block-uniform)
#pragma unroll
    for (int i = 0; i < 8; i++) {
        const int r = row0 + tm + i;
        const int b = r >> 11, s = r & (S - 1);
#pragma unroll
        for (int j = 0; j < 8; j++) {
            const int c  = col0 + tn + j - part * D;
            const int h  = c >> 6, dk = c & 63;
            const float v = acc[i][j];
            if (part == 0)      g_Q [((size_t)(b * H + h) * S  + s)  * DK + dk] = v;
            else if (part == 1) g_Kt[((size_t)(b * H + h) * DK + dk) * S  + s ] = v;
            else                g_V [((size_t)(b * H + h) * S  + s)  * DK + dk] = v;
        }
    }
}

// ---------------------------------------------------------------------------
// K2: fused attention. Grid (S/TQ=128, B=4, 2), 256 threads, ~197 KB smem.
// z selects head group: z=0 -> h 0..3 accumulating into attn_out,
//                       z=1 -> h 4..7 accumulating into g_attn2.
// ---------------------------------------------------------------------------
__global__ __launch_bounds__(256, 1) void k2_attn(
    const float* __restrict__ mask, float* __restrict__ attn_out)
{
    using namespace cfg;
    extern __shared__ float sm[];
    float* Ss  = sm;                      // [TQ][SROW]  scores / probs
    float* KVs = Ss + TQ * SROW;          // K chunk / V chunk / partials
    float* Qs  = KVs + DK * TK;           // [DK][20]    d-major Q tile

    const int qt = blockIdx.x;
    const int b  = blockIdx.y;
    const int hz = blockIdx.z;            // head group
    const int h0 = hz * HGRP;
    const int q0 = qt * TQ;
    const int t  = threadIdx.x;

    float* __restrict__ attn_dst = (hz == 0)
        ? attn_out : g_attn2;

    const int qi = t >> 6;                // 0..3
    const int ki = t & 63;                // 0..63
    const int kq  = t >> 6;               // 0..3  k-quarter group
    const int qg4 = ((t >> 4) & 3) << 2;  // q row base
    const int cg4 = (t & 15) << 2;        // col base
    const int w = t >> 5, lane = t & 31;

    float4 pf[16];

    for (int hh = 0; hh < HGRP; hh++) {
        const int h  = h0 + hh;
        const int bh = b * H + h;
        const float* __restrict__ Qg  = g_Q  + ((size_t)bh * S + q0) * DK;
        const float* __restrict__ Ktg = g_Kt + (size_t)bh * DK * S;
        const float* __restrict__ Vg  = g_V  + (size_t)bh * S * DK;

#pragma unroll
        for (int i = 0; i < 4; i++) {
            int p = t + i * 256;
            int q = p >> 6, d = p & 63;
            Qs[d * 20 + q] = Qg[q * DK + d];
        }

#pragma unroll
        for (int i = 0; i < 16; i++) {
            int p4 = t + (i << 8);
            pf[i] = *(const float4*)&Ktg[(size_t)(p4 >> 6) * S + ((p4 & 63) << 2)];
        }

        // ================= QK^T over 8 chunks =================
        for (int c = 0; c < NCH; c++) {
            const int kc = c * TK;
            __syncthreads();
#pragma unroll
            for (int i = 0; i < 16; i++) {
                int p4 = t + (i << 8);
                *(float4*)&KVs[(p4 >> 6) * TK + ((p4 & 63) << 2)] = pf[i];
            }
            if (c < NCH - 1) {
#pragma unroll
                for (int i = 0; i < 16; i++) {
                    int p4 = t + (i << 8);
                    pf[i] = *(const float4*)&Ktg[(size_t)(p4 >> 6) * S + kc + TK + ((p4 & 63) << 2)];
                }
            } else {
#pragma unroll
                for (int i = 0; i < 16; i++) {
                    int p4 = t + (i << 8);
                    pf[i] = *(const float4*)&Vg[(size_t)(p4 >> 4) * DK + ((p4 & 15) << 2)];
                }
            }
            __syncthreads();

            float acc[4][4];
#pragma unroll
            for (int i = 0; i < 4; i++)
#pragma unroll
                for (int j = 0; j < 4; j++) acc[i][j] = 0.f;

#pragma unroll
            for (int d = 0; d < DK; d++) {
                const float4 kv = *(const float4*)&KVs[d * TK + (ki << 2)];
                const float4 qv = *(const float4*)&Qs[d * 20 + (qi << 2)];
                acc[0][0] = fmaf(qv.x, kv.x, acc[0][0]);
                acc[0][1] = fmaf(qv.x, kv.y, acc[0][1]);
                acc[0][2] = fmaf(qv.x, kv.z, acc[0][2]);
                acc[0][3] = fmaf(qv.x, kv.w, acc[0][3]);
                acc[1][0] = fmaf(qv.y, kv.x, acc[1][0]);
                acc[1][1] = fmaf(qv.y, kv.y, acc[1][1]);
                acc[1][2] = fmaf(qv.y, kv.z, acc[1][2]);
                acc[1][3] = fmaf(qv.y, kv.w, acc[1][3]);
                acc[2][0] = fmaf(qv.z, kv.x, acc[2][0]);
                acc[2][1] = fmaf(qv.z, kv.y, acc[2][1]);
                acc[2][2] = fmaf(qv.z, kv.z, acc[2][2]);
                acc[2][3] = fmaf(qv.z, kv.w, acc[2][3]);
                acc[3][0] = fmaf(qv.w, kv.x, acc[3][0]);
                acc[3][1] = fmaf(qv.w, kv.y, acc[3][1]);
                acc[3][2] = fmaf(qv.w, kv.z, acc[3][2]);
                acc[3][3] = fmaf(qv.w, kv.w, acc[3][3]);
            }

#pragma unroll
            for (int i = 0; i < 4; i++) {
                const int q = (qi << 2) + i;
                const float4 mk = *(const float4*)&mask[(size_t)(q0 + q) * S + kc + (ki << 2)];
                float4 o;
                o.x = fmaf(acc[i][0], SCALE, mk.x);
                o.y = fmaf(acc[i][1], SCALE, mk.y);
                o.z = fmaf(acc[i][2], SCALE, mk.z);
                o.w = fmaf(acc[i][3], SCALE, mk.w);
                *(float4*)&Ss[q * SROW + kc + (ki << 2)] = o;
            }
        }
        __syncthreads();

        // stage V chunk 0; prefetch V chunk 1
#pragma unroll
        for (int i = 0; i < 16; i++) {
            int p4 = t + (i << 8);
            *(float4*)&KVs[(p4 >> 4) * DK + ((p4 & 15) << 2)] = pf[i];
        }
#pragma unroll
        for (int i = 0; i < 16; i++) {
            int p4 = t + (i << 8);
            pf[i] = *(const float4*)&Vg[(size_t)(TK + (p4 >> 4)) * DK + ((p4 & 15) << 2)];
        }

        // ---- softmax + attn partial RMW: warp w handles rows 2w, 2w+1 ----
#pragma unroll
        for (int rr = 0; rr < 2; rr++) {
            const int q = w * 2 + rr;
            float* row = Ss + q * SROW;
            float m = -1e30f;
            for (int i = lane; i < S; i += 32) m = fmaxf(m, row[i]);
#pragma unroll
            for (int o = 16; o; o >>= 1) m = fmaxf(m, __shfl_xor_sync(0xFFFFFFFFu, m, o));
            float l = 0.f;
            for (int i = lane; i < S; i += 32) {
                float e = __expf(row[i] - m);
                row[i] = e;
                l += e;
            }
#pragma unroll
            for (int o = 16; o; o >>= 1) l += __shfl_xor_sync(0xFFFFFFFFu, l, o);
            const float inv = 1.f / l;

            float* __restrict__ arow = attn_dst + ((size_t)b * S + q0 + q) * S;
            for (int i = lane * 4; i < S; i += 128) {
                float4 e = *(float4*)&row[i];
                e.x *= inv; e.y *= inv; e.z *= inv; e.w *= inv;
                *(float4*)&row[i] = e;
                float4 a;
                a.x = e.x * 0.125f; a.y = e.y * 0.125f;
                a.z = e.z * 0.125f; a.w = e.w * 0.125f;
                if (hh > 0) {
                    float4 prev = *(float4*)&arow[i];
                    a.x += prev.x; a.y += prev.y; a.z += prev.z; a.w += prev.w;
                }
                *(float4*)&arow[i] = a;
            }
        }
        __syncthreads();

        // ================= PV over 8 chunks (k-quartered partials) ==========
        float4 cacc[4];
#pragma unroll
        for (int i = 0; i < 4; i++) cacc[i] = make_float4(0.f, 0.f, 0.f, 0.f);

        for (int c = 0; c < NCH; c++) {
            const int vc = c * TK;
            const int kb = vc + (kq << 6);
#pragma unroll
            for (int kk = 0; kk < 64; kk += 4) {
                const float4 v0 = *(const float4*)&KVs[((kq << 6) + kk + 0) * DK + cg4];
                const float4 v1 = *(const float4*)&KVs[((kq << 6) + kk + 1) * DK + cg4];
                const float4 v2 = *(const float4*)&KVs[((kq << 6) + kk + 2) * DK + cg4];
                const float4 v3 = *(const float4*)&KVs[((kq << 6) + kk + 3) * DK + cg4];
#pragma unroll
                for (int i = 0; i < 4; i++) {
                    const float4 p = *(const float4*)&Ss[(qg4 + i) * SROW + kb + kk];
                    cacc[i].x = fmaf(p.x, v0.x, cacc[i].x);
                    cacc[i].y = fmaf(p.x, v0.y, cacc[i].y);
                    cacc[i].z = fmaf(p.x, v0.z, cacc[i].z);
                    cacc[i].w = fmaf(p.x, v0.w, cacc[i].w);
                    cacc[i].x = fmaf(p.y, v1.x, cacc[i].x);
                    cacc[i].y = fmaf(p.y, v1.y, cacc[i].y);
                    cacc[i].z = fmaf(p.y, v1.z, cacc[i].z);
                    cacc[i].w = fmaf(p.y, v1.w, cacc[i].w);
                    cacc[i].x = fmaf(p.z, v2.x, cacc[i].x);
                    cacc[i].y = fmaf(p.z, v2.y, cacc[i].y);
                    cacc[i].z = fmaf(p.z, v2.z, cacc[i].z);
                    cacc[i].w = fmaf(p.z, v2.w, cacc[i].w);
                    cacc[i].x = fmaf(p.w, v3.x, cacc[i].x);
                    cacc[i].y = fmaf(p.w, v3.y, cacc[i].y);
                    cacc[i].z = fmaf(p.w, v3.z, cacc[i].z);
                    cacc[i].w = fmaf(p.w, v3.w, cacc[i].w);
                }
            }
            if (c < NCH - 1) {
                __syncthreads();
#pragma unroll
                for (int i = 0; i < 16; i++) {
                    int p4 = t + (i << 8);
                    *(float4*)&KVs[(p4 >> 4) * DK + ((p4 & 15) << 2)] = pf[i];
                }
                if (c < NCH - 2) {
#pragma unroll
                    for (int i = 0; i < 16; i++) {
                        int p4 = t + (i << 8);
                        pf[i] = *(const float4*)&Vg[(size_t)((vc + 2 * TK) + (p4 >> 4)) * DK + ((p4 & 15) << 2)];
                    }
                }
                __syncthreads();
            }
        }

        // ---- reduce the 4 k-quarter partials through smem ----
        __syncthreads();
#pragma unroll
        for (int i = 0; i < 4; i++)
            *(float4*)&KVs[(kq << 10) + (qg4 + i) * DK + cg4] = cacc[i];
        __syncthreads();
        {
            const int q  = t >> 4;
            const int c4 = (t & 15) << 2;
            float4 s0 = *(const float4*)&KVs[0 * 1024 + q * DK + c4];
            float4 s1 = *(const float4*)&KVs[1 * 1024 + q * DK + c4];
            float4 s2 = *(const float4*)&KVs[2 * 1024 + q * DK + c4];
            float4 s3 = *(const float4*)&KVs[3 * 1024 + q * DK + c4];
            float4 o;
            o.x = (s0.x + s1.x) + (s2.x + s3.x);
            o.y = (s0.y + s1.y) + (s2.y + s3.y);
            o.z = (s0.z + s1.z) + (s2.z + s3.z);
            o.w = (s0.w + s1.w) + (s2.w + s3.w);
            *(float4*)&g_ctx[((size_t)b * S + q0 + q) * D + h * DK + c4] = o;
        }
    }
}

// ---------------------------------------------------------------------------
// K3: attn_out += g_attn2  (merge the h 4-7 partial sums; pure bandwidth)
// ---------------------------------------------------------------------------
__global__ __launch_bounds__(256) void k3_merge(float* __restrict__ attn_out)
{
    using namespace cfg;
    const size_t i4 = (size_t)blockIdx.x * 256 + threadIdx.x;
    float4 a = ((const float4*)g_attn2)[i4];
    float4 o = ((float4*)attn_out)[i4];
    o.x += a.x; o.y += a.y; o.z += a.z; o.w += a.w;
    ((float4*)attn_out)[i4] = o;
}

// ---------------------------------------------------------------------------
// K5: out[8192,512] = ctx @ Wout (FFMA; reverted from the slower mma version)
// ---------------------------------------------------------------------------
__global__ __launch_bounds__(256) void k5_out(
    const float* __restrict__ Wout, float* __restrict__ out)
{
    using namespace cfg;
    constexpr int BM = 128, BN = 128, BK = 16;
    __shared__ float As[BK][BM + 4];
    __shared__ float Bs[BK][BN];

    const int row0 = blockIdx.x * BM;
    const int col0 = blockIdx.y * BN;
    const int t  = threadIdx.x;
    const int tm = (t >> 4) << 3;
    const int tn = (t & 15) << 3;

    float acc[8][8];
#pragma unroll
    for (int i = 0; i < 8; i++)
#pragma unroll
        for (int j = 0; j < 8; j++) acc[i][j] = 0.f;

    for (int k0 = 0; k0 < D; k0 += BK) {
#pragma unroll
        for (int i = 0; i < 8; i++) {
            int p = t + i * 256;
            int m = p >> 4, k = p & 15;
            As[k][m] = g_ctx[(size_t)(row0 + m) * D + k0 + k];
        }
#pragma unroll
        for (int i = 0; i < 8; i++) {
            int p = t + i * 256;
            int k = p >> 7, n = p & 127;
            Bs[k][n] = Wout[(size_t)(k0 + k) * D + col0 + n];
        }
        __syncthreads();
#pragma unroll
        for (int k = 0; k < BK; k++) {
            float a[8], b[8];
#pragma unroll
            for (int i = 0; i < 8; i++) a[i] = As[k][tm + i];
#pragma unroll
            for (int j = 0; j < 8; j++) b[j] = Bs[k][tn + j];
#pragma unroll
            for (int i = 0; i < 8; i++)
#pragma unroll
                for (int j = 0; j < 8; j++)
                    acc[i][j] = fmaf(a[i], b[j], acc[i][j]);
        }
        __syncthreads();
    }
#pragma unroll
    for (int i = 0; i < 8; i++) {
        const int r = row0 + tm + i;
#pragma unroll
        for (int j = 0; j < 8; j++)
            out[(size_t)r * D + col0 + tn + j] = acc[i][j];
    }
}

// ---------------------------------------------------------------------------
namespace {
struct CudaWarm {
    CudaWarm() {
        cudaFuncSetAttribute(k2_attn,
            cudaFuncAttributeMaxDynamicSharedMemorySize, cfg::SMEM2);
        cudaFuncAttributes a;
        cudaFuncGetAttributes(&a, (const void*)k1_qkv);
        cudaFuncGetAttributes(&a, (const void*)k2_attn);
        cudaFuncGetAttributes(&a, (const void*)k3_merge);
        cudaFuncGetAttributes(&a, (const void*)k5_out);
    }
};
CudaWarm g_warm;
}

// ---------------------------------------------------------------------------
extern "C" void kernel_launch(void* const* d_in, const int* in_sizes, int n_in,
                              void* d_out, int out_size)
{
    using namespace cfg;
    const float* Zq   = (const float*)d_in[0];
    const float* Zkv  = (const float*)d_in[1];
    const float* mask = (const float*)d_in[2];
    const float* Wqkv = (const float*)d_in[3];
    const float* Wout = (const float*)d_in[4];

    float* out       = (float*)d_out;
    float* attn_mean = out + (size_t)B * S * D;

    cudaFuncSetAttribute(k2_attn,
        cudaFuncAttributeMaxDynamicSharedMemorySize, SMEM2);

    k1_qkv<<<dim3(MROWS / 128, N3 / 128), 256>>>(Zq, Zkv, Wqkv);
    k2_attn<<<dim3(S / TQ, B, 2), 256, SMEM2>>>(mask, attn_mean);
    k3_merge<<<(int)((size_t)B * S * S / 4 / 256), 256>>>(attn_mean);
    k5_out<<<dim3(MROWS / 128, D / 128), 256>>>(Wout, out);
}